// round 1
// baseline (speedup 1.0000x reference)
#include <cuda_runtime.h>
#include <cuda_bf16.h>

#define N      512
#define DIM    256
#define SCAL   10.0f
#define EPSV   1e-12f

// __device__ scratch (no allocations allowed in kernel_launch)
__device__ float g_sq[N];
__device__ float g_D[N * N];
__device__ float g_partial[N];   // per-anchor loss sum
__device__ float g_pcount[N];    // per-anchor triplet count

// ---------------------------------------------------------------------------
// Kernel 1: squared norms. One warp per row.
// ---------------------------------------------------------------------------
__global__ void k_sqnorm(const float* __restrict__ feat) {
    int i = blockIdx.x;
    int lane = threadIdx.x;           // 32 threads
    const float4* row = reinterpret_cast<const float4*>(feat + i * DIM);
    float s = 0.f;
    #pragma unroll
    for (int k = lane; k < DIM / 4; k += 32) {
        float4 v = row[k];
        s += v.x * v.x + v.y * v.y + v.z * v.z + v.w * v.w;
    }
    #pragma unroll
    for (int o = 16; o > 0; o >>= 1) s += __shfl_xor_sync(0xffffffffu, s, o);
    if (lane == 0) g_sq[i] = s;
}

// ---------------------------------------------------------------------------
// Kernel 2: pairwise distances. Block per row i; warp per column j (strided).
// ---------------------------------------------------------------------------
__global__ void k_dist(const float* __restrict__ feat) {
    __shared__ float fi[DIM];
    const int i    = blockIdx.x;
    const int tid  = threadIdx.x;     // 256 threads = 8 warps
    const int warp = tid >> 5;
    const int lane = tid & 31;

    for (int k = tid; k < DIM; k += 256) fi[k] = feat[i * DIM + k];
    __syncthreads();

    const float sqi = g_sq[i];
    for (int j = warp; j < N; j += 8) {
        const float4* fj = reinterpret_cast<const float4*>(feat + j * DIM);
        float dot = 0.f;
        #pragma unroll
        for (int k = lane; k < DIM / 4; k += 32) {
            float4 v = fj[k];
            dot += v.x * fi[4 * k + 0] + v.y * fi[4 * k + 1]
                 + v.z * fi[4 * k + 2] + v.w * fi[4 * k + 3];
        }
        #pragma unroll
        for (int o = 16; o > 0; o >>= 1) dot += __shfl_xor_sync(0xffffffffu, dot, o);
        if (lane == 0) {
            float sq = sqi + g_sq[j] - 2.f * dot;
            g_D[i * N + j] = sqrtf(fmaxf(sq, EPSV));
        }
    }
}

// ---------------------------------------------------------------------------
// Kernel 3: triplet sum. Block per anchor a. Deterministic per-block partials.
// ---------------------------------------------------------------------------
__global__ void k_triplet(const int* __restrict__ y) {
    __shared__ float Drow[N];
    __shared__ int   ys[N];
    __shared__ float red_s[256];
    __shared__ float red_c[256];

    const int a   = blockIdx.x;
    const int tid = threadIdx.x;      // 256 threads

    for (int j = tid; j < N; j += 256) {
        Drow[j] = g_D[a * N + j];
        ys[j]   = y[j];
    }
    __syncthreads();

    const int ya = ys[a];

    // negatives handled by this thread (strided subset), count them once
    float negcnt = 0.f;
    for (int n = tid; n < N; n += 256)
        if (ys[n] != ya) negcnt += 1.f;

    float acc  = 0.f;
    float npos = 0.f;
    for (int p = 0; p < N; ++p) {
        if (p == a || ys[p] != ya) continue;
        npos += 1.f;
        const float dp = Drow[p];
        #pragma unroll 2
        for (int n = tid; n < N; n += 256) {
            if (ys[n] != ya) {
                float x = SCAL * (dp - Drow[n]);
                acc += 1.f / (1.f + __expf(-x));
            }
        }
    }

    red_s[tid] = acc;
    red_c[tid] = negcnt;
    __syncthreads();
    #pragma unroll
    for (int s = 128; s > 0; s >>= 1) {
        if (tid < s) {
            red_s[tid] += red_s[tid + s];
            red_c[tid] += red_c[tid + s];
        }
        __syncthreads();
    }
    if (tid == 0) {
        g_partial[a] = red_s[0];
        g_pcount[a]  = npos * red_c[0];   // npos * total negatives
    }
}

// ---------------------------------------------------------------------------
// Kernel 4: final reduction over 512 anchors.
// ---------------------------------------------------------------------------
__global__ void k_final(float* __restrict__ out) {
    __shared__ float rs[N];
    __shared__ float rc[N];
    const int tid = threadIdx.x;      // 512 threads
    rs[tid] = g_partial[tid];
    rc[tid] = g_pcount[tid];
    __syncthreads();
    #pragma unroll
    for (int s = 256; s > 0; s >>= 1) {
        if (tid < s) { rs[tid] += rs[tid + s]; rc[tid] += rc[tid + s]; }
        __syncthreads();
    }
    if (tid == 0) out[0] = rs[0] / rc[0];
}

// ---------------------------------------------------------------------------
extern "C" void kernel_launch(void* const* d_in, const int* in_sizes, int n_in,
                              void* d_out, int out_size) {
    const float* feat = (const float*)d_in[0];
    // d_in[1] = logits (unused by the loss)
    const int*   y    = (const int*)d_in[2];
    float*       out  = (float*)d_out;

    k_sqnorm <<<N,  32>>>(feat);
    k_dist   <<<N, 256>>>(feat);
    k_triplet<<<N, 256>>>(y);
    k_final  <<<1, N>>>(out);
}

// round 2
// speedup vs baseline: 2.7421x; 2.7421x over previous
#include <cuda_runtime.h>
#include <cuda_bf16.h>

#define N      512
#define DIM    256
#define TI     8          // anchors per dist block
#define JCHUNK 128        // j per dist block
#define SCAL   10.0f
#define EPSV   1e-12f

// __device__ scratch (no allocations allowed anywhere)
__device__ float    g_D[N * N];
__device__ float    g_partial[N];
__device__ float    g_pcount[N];
__device__ unsigned g_done = 0;

__device__ __forceinline__ float ex2a(float x) {
    float y; asm("ex2.approx.ftz.f32 %0, %1;" : "=f"(y) : "f"(x)); return y;
}
__device__ __forceinline__ float rcpa(float x) {
    float y; asm("rcp.approx.ftz.f32 %0, %1;" : "=f"(y) : "f"(x)); return y;
}

// ---------------------------------------------------------------------------
// Kernel 1: pairwise distances, tiled. Block = 8 anchors x 128 columns.
// Grid (64, 4). Anchor rows register-cached per lane; warp computes 8
// distances per j visit via 8 parallel butterfly reductions.
// ---------------------------------------------------------------------------
__global__ void __launch_bounds__(256)
k_dist(const float* __restrict__ feat) {
    __shared__ float4 fa4[TI * 64];          // 8 rows x 64 float4 = 8 KB
    __shared__ float  Dtile[TI][JCHUNK];     // 4 KB

    const int itile = blockIdx.x;            // 0..63
    const int jbase = blockIdx.y * JCHUNK;   // 0..383
    const int tid   = threadIdx.x;
    const int warp  = tid >> 5;
    const int lane  = tid & 31;

    const float4* f4 = reinterpret_cast<const float4*>(feat);

    for (int v = tid; v < TI * 64; v += 256)
        fa4[v] = f4[itile * (TI * 64) + v];
    __syncthreads();

    // register-cache this lane's slice of the 8 anchor rows
    float4 a0[TI], a1[TI];
    #pragma unroll
    for (int i = 0; i < TI; ++i) {
        a0[i] = fa4[i * 64 + lane];
        a1[i] = fa4[i * 64 + 32 + lane];
    }

    for (int t = 0; t < JCHUNK / 8; ++t) {
        const int jj = warp + t * 8;         // 0..127
        const int j  = jbase + jj;
        const float4 b0 = f4[j * 64 + lane];
        const float4 b1 = f4[j * 64 + 32 + lane];

        float acc[TI];
        #pragma unroll
        for (int i = 0; i < TI; ++i) {
            float d, s;
            d = a0[i].x - b0.x; s  = d * d;
            d = a0[i].y - b0.y; s += d * d;
            d = a0[i].z - b0.z; s += d * d;
            d = a0[i].w - b0.w; s += d * d;
            d = a1[i].x - b1.x; s += d * d;
            d = a1[i].y - b1.y; s += d * d;
            d = a1[i].z - b1.z; s += d * d;
            d = a1[i].w - b1.w; s += d * d;
            acc[i] = s;
        }
        #pragma unroll
        for (int o = 16; o > 0; o >>= 1) {
            #pragma unroll
            for (int i = 0; i < TI; ++i)
                acc[i] += __shfl_xor_sync(0xffffffffu, acc[i], o);
        }
        if (lane == 0) {
            #pragma unroll
            for (int i = 0; i < TI; ++i)
                Dtile[i][jj] = sqrtf(fmaxf(acc[i], EPSV));
        }
    }
    __syncthreads();

    // coalesced writeback of the 8 x 128 tile
    const float* Dt = &Dtile[0][0];
    for (int v = tid; v < TI * JCHUNK; v += 256) {
        int i = v / JCHUNK, jj = v % JCHUNK;
        g_D[(itile * TI + i) * N + jbase + jj] = Dt[v];
    }
}

// ---------------------------------------------------------------------------
// Kernel 2: triplet sum per anchor + fused final reduction (last block).
// ---------------------------------------------------------------------------
__global__ void __launch_bounds__(256)
k_triplet(const int* __restrict__ y, float* __restrict__ out) {
    __shared__ float Dr[N];        // D row, pre-scaled by SCAL*log2(e)
    __shared__ int   ys[N];
    __shared__ float posD[128];    // scaled distances of positives
    __shared__ int   npos_s, nneg_s;
    __shared__ float red[256];
    __shared__ int   last_s;

    const int a    = blockIdx.x;
    const int tid  = threadIdx.x;
    const int warp = tid >> 5;
    const int lane = tid & 31;
    const float K  = SCAL * 1.4426950408889634f;   // scale * log2(e)

    for (int j = tid; j < N; j += 256) {
        Dr[j] = g_D[a * N + j] * K;
        ys[j] = y[j];
    }
    __syncthreads();

    const int ya = ys[a];

    if (warp == 0) {
        int cnt = 0, same = 0;
        for (int base = 0; base < N; base += 32) {
            int  j  = base + lane;
            bool sc = (ys[j] == ya);
            bool v  = sc && (j != a);
            unsigned mv = __ballot_sync(0xffffffffu, v);
            if (v) posD[cnt + __popc(mv & ((1u << lane) - 1u))] = Dr[j];
            cnt  += __popc(mv);
            same += __popc(__ballot_sync(0xffffffffu, sc));
        }
        if (lane == 0) { npos_s = cnt; nneg_s = N - same; }
    }
    __syncthreads();

    const int   npos = npos_s;
    const float dn0  = Dr[tid];
    const float dn1  = Dr[tid + 256];
    const float m0   = (ys[tid]       != ya) ? 1.f : 0.f;
    const float m1   = (ys[tid + 256] != ya) ? 1.f : 0.f;

    float acc = 0.f;
    for (int p = 0; p < npos; ++p) {
        const float dp = posD[p];
        // sigmoid(scale*(Dp - Dn)) = 1 / (1 + 2^(K*Dn - K*Dp))
        float t0 = ex2a(dn0 - dp);
        float t1 = ex2a(dn1 - dp);
        acc += m0 * rcpa(1.f + t0);
        acc += m1 * rcpa(1.f + t1);
    }

    red[tid] = acc;
    __syncthreads();
    #pragma unroll
    for (int s = 128; s > 0; s >>= 1) {
        if (tid < s) red[tid] += red[tid + s];
        __syncthreads();
    }

    if (tid == 0) {
        g_partial[a] = red[0];
        g_pcount[a]  = (float)(npos * nneg_s);
        __threadfence();
        unsigned t = atomicAdd(&g_done, 1u);
        last_s = (t == N - 1);
    }
    __syncthreads();

    if (last_s) {
        __threadfence();
        // deterministic: fixed per-thread pairing + fixed tree order
        float s = __ldcg(&g_partial[tid]) + __ldcg(&g_partial[tid + 256]);
        float c = __ldcg(&g_pcount[tid])  + __ldcg(&g_pcount[tid + 256]);
        red[tid] = s;
        __syncthreads();
        #pragma unroll
        for (int st = 128; st > 0; st >>= 1) {
            if (tid < st) red[tid] += red[tid + st];
            __syncthreads();
        }
        const float tot = red[0];
        __syncthreads();
        red[tid] = c;
        __syncthreads();
        #pragma unroll
        for (int st = 128; st > 0; st >>= 1) {
            if (tid < st) red[tid] += red[tid + st];
            __syncthreads();
        }
        if (tid == 0) {
            out[0] = tot / red[0];
            g_done = 0;                 // reset for next graph replay
        }
    }
}

// ---------------------------------------------------------------------------
extern "C" void kernel_launch(void* const* d_in, const int* in_sizes, int n_in,
                              void* d_out, int out_size) {
    const float* feat = (const float*)d_in[0];
    // d_in[1] = logits (unused by the loss)
    const int*   y    = (const int*)d_in[2];
    float*       out  = (float*)d_out;

    k_dist   <<<dim3(64, 4), 256>>>(feat);
    k_triplet<<<N, 256>>>(y, out);
}

// round 3
// speedup vs baseline: 3.4663x; 1.2641x over previous
#include <cuda_runtime.h>
#include <cuda_bf16.h>

#define N      512
#define DIM    256
#define SCAL   10.0f
#define EPSV   1e-12f
#define KLOG2E 14.4269504088896340736f   // SCAL * log2(e)

// tiles for dist kernel
#define TI 32      // i rows per block
#define TJ 64      // j cols per block
#define TK 64      // k chunk

__device__ float    g_D[N * N];
__device__ float    g_partial[N];
__device__ float    g_pcount[N];
__device__ unsigned g_done = 0;

__device__ __forceinline__ float ex2a(float x) {
    float y; asm("ex2.approx.ftz.f32 %0, %1;" : "=f"(y) : "f"(x)); return y;
}
__device__ __forceinline__ float rcpa(float x) {
    float y; asm("rcp.approx.ftz.f32 %0, %1;" : "=f"(y) : "f"(x)); return y;
}

// ---------------------------------------------------------------------------
// Kernel 1: D = sqrt(max(sq_i + sq_j - 2*feat@feat^T, eps)), GEMM-tiled.
// Grid (16,8) = 128 blocks; block computes a 32(i) x 64(j) tile.
// 256 threads as 16x16; each thread owns a 2x4 micro-tile.
// ---------------------------------------------------------------------------
__global__ void __launch_bounds__(256)
k_dist(const float* __restrict__ feat) {
    __shared__ float As [TI][TK + 4];   // row-major, padded (16B-aligned rows)
    __shared__ float Bst[TK][TJ + 4];   // k-major (transposed), padded
    __shared__ float sqi[TI];
    __shared__ float sqj[TJ];

    const int tid = threadIdx.x;
    const int i0  = blockIdx.x * TI;
    const int j0  = blockIdx.y * TJ;
    const int tx  = tid & 15;
    const int ty  = tid >> 4;

    const float4* f4 = reinterpret_cast<const float4*>(feat);  // row pitch 64 f4

    // ---- prologue: squared norms for the 32 i-rows and 64 j-rows ----
    if (tid < 192) {
        const int rid  = tid >> 1;            // 0..95
        const int half = tid & 1;
        const int grow = (rid < TI) ? (i0 + rid) : (j0 + rid - TI);
        float s = 0.f;
        #pragma unroll
        for (int q = 0; q < 32; ++q) {
            float4 v = f4[grow * 64 + half * 32 + q];
            s += v.x * v.x + v.y * v.y + v.z * v.z + v.w * v.w;
        }
        s += __shfl_xor_sync(0xffffffffu, s, 1);
        if (half == 0) {
            if (rid < TI) sqi[rid] = s; else sqj[rid - TI] = s;
        }
    }

    float acc[2][4] = {};

    #pragma unroll
    for (int kc = 0; kc < DIM / TK; ++kc) {
        __syncthreads();
        // load A tile: 32 rows x 16 f4 = 512 f4, 2 per thread
        {
            int v = tid;
            #pragma unroll
            for (int s = 0; s < 2; ++s, v += 256) {
                int i = v >> 4, kq = v & 15;
                float4 a = f4[(i0 + i) * 64 + kc * 16 + kq];
                *reinterpret_cast<float4*>(&As[i][4 * kq]) = a;
            }
        }
        // load B tile transposed: 64 rows x 16 f4 = 1024 f4, 4 per thread
        {
            int v = tid;
            #pragma unroll
            for (int s = 0; s < 4; ++s, v += 256) {
                int j = v & 63, kq = v >> 6;
                float4 b = f4[(j0 + j) * 64 + kc * 16 + kq];
                Bst[4 * kq + 0][j] = b.x;
                Bst[4 * kq + 1][j] = b.y;
                Bst[4 * kq + 2][j] = b.z;
                Bst[4 * kq + 3][j] = b.w;
            }
        }
        __syncthreads();

        #pragma unroll
        for (int k = 0; k < TK; ++k) {
            const float a0 = As[ty * 2 + 0][k];
            const float a1 = As[ty * 2 + 1][k];
            const float4 b = *reinterpret_cast<const float4*>(&Bst[k][tx * 4]);
            acc[0][0] += a0 * b.x; acc[0][1] += a0 * b.y;
            acc[0][2] += a0 * b.z; acc[0][3] += a0 * b.w;
            acc[1][0] += a1 * b.x; acc[1][1] += a1 * b.y;
            acc[1][2] += a1 * b.z; acc[1][3] += a1 * b.w;
        }
    }
    __syncthreads();

    // epilogue: D = sqrt(max(sqi + sqj - 2*dot, eps))
    #pragma unroll
    for (int r = 0; r < 2; ++r) {
        const int gi = i0 + ty * 2 + r;
        const float si = sqi[ty * 2 + r];
        float4 o;
        o.x = sqrtf(fmaxf(si + sqj[tx * 4 + 0] - 2.f * acc[r][0], EPSV));
        o.y = sqrtf(fmaxf(si + sqj[tx * 4 + 1] - 2.f * acc[r][1], EPSV));
        o.z = sqrtf(fmaxf(si + sqj[tx * 4 + 2] - 2.f * acc[r][2], EPSV));
        o.w = sqrtf(fmaxf(si + sqj[tx * 4 + 3] - 2.f * acc[r][3], EPSV));
        *reinterpret_cast<float4*>(&g_D[gi * N + j0 + tx * 4]) = o;
    }
}

// ---------------------------------------------------------------------------
// Kernel 2: triplet sum per anchor + fused final reduction (last block).
// sigmoid(K(Dp-Dn)) = 1/(1 + 2^{x_n-c} * 2^{c-x_p}),  x = K*log2e*D.
// 256 threads; thread t owns negatives t and t+256.
// ---------------------------------------------------------------------------
__global__ void __launch_bounds__(256)
k_triplet(const int* __restrict__ y, float* __restrict__ out) {
    __shared__ float xsh[N];
    __shared__ int   ysh[N];
    __shared__ float posR[128];
    __shared__ float wsum[8];
    __shared__ int   npos_s, nneg_s, last_s;

    const int a    = blockIdx.x;
    const int tid  = threadIdx.x;
    const int warp = tid >> 5;
    const int lane = tid & 31;

    const float x0 = g_D[a * N + tid]       * KLOG2E;
    const float x1 = g_D[a * N + tid + 256] * KLOG2E;
    const int   y0 = y[tid];
    const int   y1 = y[tid + 256];
    const int   ya = __ldg(&y[a]);
    xsh[tid] = x0; xsh[tid + 256] = x1;
    ysh[tid] = y0; ysh[tid + 256] = y1;
    __syncthreads();

    const float c = xsh[(a + 1) & (N - 1)];

    if (warp == 0) {
        int cnt = 0, same = 0;
        for (int base = 0; base < N; base += 32) {
            int  j  = base + lane;
            bool sc = (ysh[j] == ya);
            bool v  = sc && (j != a);
            unsigned mv = __ballot_sync(0xffffffffu, v);
            if (v) {
                int slot = cnt + __popc(mv & ((1u << lane) - 1u));
                posR[slot] = fmaxf(ex2a(c - xsh[j]), 1e-30f);
            }
            cnt  += __popc(mv);
            same += __popc(__ballot_sync(0xffffffffu, sc));
        }
        if (lane == 0) { npos_s = cnt; nneg_s = N - same; }
    }
    __syncthreads();

    const float INF = __int_as_float(0x7f800000);
    const float e0  = (y0 != ya) ? ex2a(x0 - c) : INF;
    const float e1  = (y1 != ya) ? ex2a(x1 - c) : INF;
    const int npos  = npos_s;

    float acc = 0.f;
    for (int p = 0; p < npos; ++p) {
        const float rp = posR[p];
        acc += rcpa(fmaf(e0, rp, 1.f));
        acc += rcpa(fmaf(e1, rp, 1.f));
    }

    // warp reduce, then cross-warp
    #pragma unroll
    for (int o = 16; o > 0; o >>= 1) acc += __shfl_xor_sync(0xffffffffu, acc, o);
    if (lane == 0) wsum[warp] = acc;
    __syncthreads();

    if (tid == 0) {
        float s = 0.f;
        #pragma unroll
        for (int w = 0; w < 8; ++w) s += wsum[w];
        g_partial[a] = s;
        g_pcount[a]  = (float)(npos * nneg_s);
        __threadfence();
        unsigned t = atomicAdd(&g_done, 1u);
        last_s = (t == N - 1);
    }
    __syncthreads();

    if (last_s) {
        __threadfence();
        __shared__ float red[256];
        float s = __ldcg(&g_partial[tid]) + __ldcg(&g_partial[tid + 256]);
        float cc = __ldcg(&g_pcount[tid]) + __ldcg(&g_pcount[tid + 256]);
        red[tid] = s;
        __syncthreads();
        #pragma unroll
        for (int st = 128; st > 0; st >>= 1) {
            if (tid < st) red[tid] += red[tid + st];
            __syncthreads();
        }
        const float tot = red[0];
        __syncthreads();
        red[tid] = cc;
        __syncthreads();
        #pragma unroll
        for (int st = 128; st > 0; st >>= 1) {
            if (tid < st) red[tid] += red[tid + st];
            __syncthreads();
        }
        if (tid == 0) {
            out[0] = tot / red[0];
            g_done = 0;                 // reset for next graph replay
        }
    }
}

// ---------------------------------------------------------------------------
extern "C" void kernel_launch(void* const* d_in, const int* in_sizes, int n_in,
                              void* d_out, int out_size) {
    const float* feat = (const float*)d_in[0];
    // d_in[1] = logits (unused by the loss)
    const int*   y    = (const int*)d_in[2];
    float*       out  = (float*)d_out;

    k_dist   <<<dim3(16, 8), 256>>>(feat);
    k_triplet<<<N, 256>>>(y, out);
}